// round 1
// baseline (speedup 1.0000x reference)
#include <cuda_runtime.h>

// BinsCombinerLayer: out[b] = (1/NUM_BINS) * sum_{n,s} inputs[b,n,s] * centroids[n,s]
// B=32768, NUM_BINS=16, BIN_SIZE=128  -> per-example row of 2048 floats dotted
// against one shared 2048-float table. HBM-bound streaming reduction.

#define B_TOTAL     32768
#define ROW_FLOATS  2048          // NUM_BINS * BIN_SIZE
#define ROW_VEC4    (ROW_FLOATS / 4)   // 512 float4 per row
#define VEC_PER_LANE (ROW_VEC4 / 32)   // 16 float4 per lane per example
#define THREADS     256
#define WARPS_PER_BLOCK (THREADS / 32)
#define INV_NUM_BINS (1.0f / 16.0f)

__global__ __launch_bounds__(THREADS)
void bins_combiner_kernel(const float* __restrict__ inputs,
                          const float* __restrict__ centroids,
                          float* __restrict__ out)
{
    __shared__ float4 sc[ROW_VEC4];   // 8 KB centroid table, block-resident

    // Cooperative centroid stage (coalesced float4)
    const float4* c4 = reinterpret_cast<const float4*>(centroids);
    for (int i = threadIdx.x; i < ROW_VEC4; i += THREADS) {
        sc[i] = c4[i];
    }
    __syncthreads();

    const int warp = threadIdx.x >> 5;
    const int lane = threadIdx.x & 31;
    const int b = blockIdx.x * WARPS_PER_BLOCK + warp;   // one example per warp

    const float4* __restrict__ row =
        reinterpret_cast<const float4*>(inputs + (size_t)b * ROW_FLOATS);

    float acc = 0.0f;
    #pragma unroll
    for (int k = 0; k < VEC_PER_LANE; ++k) {
        const int idx = lane + 32 * k;          // coalesced: warp covers 512B/group
        float4 v = row[idx];                    // 16 independent loads -> MLP=16
        float4 c = sc[idx];
        acc += v.x * c.x;
        acc += v.y * c.y;
        acc += v.z * c.z;
        acc += v.w * c.w;
    }

    // Warp butterfly reduce
    #pragma unroll
    for (int off = 16; off > 0; off >>= 1) {
        acc += __shfl_xor_sync(0xFFFFFFFFu, acc, off);
    }

    if (lane == 0) {
        out[b] = acc * INV_NUM_BINS;
    }
}

extern "C" void kernel_launch(void* const* d_in, const int* in_sizes, int n_in,
                              void* d_out, int out_size)
{
    const float* inputs    = (const float*)d_in[0];   // [32768, 16, 128] f32
    const float* centroids = (const float*)d_in[1];   // [16, 128] f32
    float* out             = (float*)d_out;           // [32768] f32

    const int grid = B_TOTAL / WARPS_PER_BLOCK;       // 4096 blocks
    bins_combiner_kernel<<<grid, THREADS>>>(inputs, centroids, out);
}